// round 1
// baseline (speedup 1.0000x reference)
#include <cuda_runtime.h>
#include <cuda_bf16.h>

// ---------------------------------------------------------------------------
// DQN_19198503813318: conv tower (shared across L) + per-landmark FC heads.
// B=512, L=6 -> BL=3072 images of (4,45,45).
//   conv0 5x5 p1 -> 43x43 -> prelu -> pool2 -> (32,21,21)
//   conv1 5x5 p1 -> 19x19 -> prelu -> pool2 -> (32,9,9)
//   conv2 4x4 p1 ->  8x8  -> prelu -> pool2 -> (64,4,4)
//   conv3 3x3 p0 ->  2x2  -> prelu          -> flatten 256
//   fc 256->128->64->4 per landmark.
// All stages fused conv+prelu+pool; smem-resident per-image direct conv.
// ---------------------------------------------------------------------------

#define BL 3072

// scratch (device globals: allocation-free per harness rules)
__device__ float g_s0[BL * 32 * 21 * 21];   // after stage0
__device__ float g_s1[BL * 32 * 9 * 9];     // after stage1
__device__ float g_s2[BL * 64 * 4 * 4];     // after stage2
__device__ float g_s3[BL * 256];            // flattened features

__device__ __forceinline__ float prelu(float v, float a) {
    return v >= 0.0f ? v : a * v;
}

// ---------------------------------------------------------------------------
// Stage 0: conv(4->32, 5x5, pad1) + prelu + pool2   in: x (BL,4,45,45)
// grid = BL, block = 224 (oc = tid&31, g = tid>>5 in 0..6 -> px = 3g..3g+2)
// smem: sIn[4][46][46] (padded) + sW[32][101]
// ---------------------------------------------------------------------------
__global__ void k_conv0(const float* __restrict__ x,
                        const float* __restrict__ w,
                        const float* __restrict__ b,
                        const float* __restrict__ ap) {
    extern __shared__ float smem[];
    float* sIn = smem;          // 4*46*46 = 8464
    float* sW  = smem + 8464;   // 32*101  = 3232
    const int bl  = blockIdx.x;
    const int tid = threadIdx.x;

    for (int i = tid; i < 8464; i += 224) sIn[i] = 0.0f;
    __syncthreads();
    const float* xb = x + bl * 8100;
    for (int i = tid; i < 8100; i += 224) {
        int ic = i / 2025;
        int r  = (i / 45) % 45;
        int c  = i % 45;
        sIn[ic * 2116 + (r + 1) * 46 + (c + 1)] = xb[i];
    }
    for (int k = tid; k < 3200; k += 224) {
        int oc = k / 100;
        sW[oc * 101 + (k % 100)] = w[k];
    }
    __syncthreads();

    const int oc = tid & 31;
    const int g  = tid >> 5;            // 0..6
    const float bias = b[oc];
    const float a = *ap;
    const float* wB = sW + oc * 101;

    for (int py = 0; py < 21; ++py) {
        float accA[6], accB[6];
#pragma unroll
        for (int j = 0; j < 6; ++j) { accA[j] = bias; accB[j] = bias; }
        const int y0 = 2 * py;
        for (int ic = 0; ic < 4; ++ic) {
            const float* inC = sIn + ic * 2116;
#pragma unroll
            for (int ky = 0; ky < 5; ++ky) {
                const float* r0 = inC + (y0 + ky) * 46 + 6 * g;
                const float* r1 = r0 + 46;
                float ra[10], rb[10];
#pragma unroll
                for (int j = 0; j < 10; ++j) { ra[j] = r0[j]; rb[j] = r1[j]; }
                const float* wv = wB + ic * 25 + ky * 5;
#pragma unroll
                for (int kx = 0; kx < 5; ++kx) {
                    float wk = wv[kx];
#pragma unroll
                    for (int j = 0; j < 6; ++j) {
                        accA[j] = fmaf(ra[j + kx], wk, accA[j]);
                        accB[j] = fmaf(rb[j + kx], wk, accB[j]);
                    }
                }
            }
        }
        float* o = g_s0 + ((bl * 32 + oc) * 21 + py) * 21 + 3 * g;
#pragma unroll
        for (int u = 0; u < 3; ++u) {
            float v0 = prelu(accA[2 * u], a);
            float v1 = prelu(accA[2 * u + 1], a);
            float v2 = prelu(accB[2 * u], a);
            float v3 = prelu(accB[2 * u + 1], a);
            o[u] = fmaxf(fmaxf(v0, v1), fmaxf(v2, v3));
        }
    }
}

// ---------------------------------------------------------------------------
// Stage 1: conv(32->32, 5x5, pad1) + prelu + pool2   in: g_s0 (BL,32,21,21)
// grid = (BL,2) [oc half], block = 432 (ocl = tid&15, py=(tid>>4)%9, g=tid/144)
// smem: sIn[32][22][22] + sW[16][801]
// ---------------------------------------------------------------------------
__global__ void k_conv1(const float* __restrict__ w,
                        const float* __restrict__ b,
                        const float* __restrict__ ap) {
    extern __shared__ float smem[];
    float* sIn = smem;             // 32*484 = 15488
    float* sW  = smem + 15488;     // 16*801 = 12816
    const int bl   = blockIdx.x;
    const int half = blockIdx.y;
    const int tid  = threadIdx.x;

    for (int i = tid; i < 15488; i += 432) sIn[i] = 0.0f;
    __syncthreads();
    const float* src = g_s0 + bl * (32 * 441);
    for (int i = tid; i < 32 * 441; i += 432) {
        int ic = i / 441;
        int r  = (i / 21) % 21;
        int c  = i % 21;
        sIn[ic * 484 + (r + 1) * 22 + (c + 1)] = src[i];
    }
    for (int k = tid; k < 16 * 800; k += 432) {
        int ocl = k / 800;
        sW[ocl * 801 + (k % 800)] = w[(half * 16 + ocl) * 800 + (k % 800)];
    }
    __syncthreads();

    const int ocl = tid & 15;
    const int py  = (tid >> 4) % 9;
    const int g   = tid / 144;       // 0..2
    const int oc  = half * 16 + ocl;
    const float bias = b[oc];
    const float a = *ap;
    const float* wB = sW + ocl * 801;

    float accA[6], accB[6];
#pragma unroll
    for (int j = 0; j < 6; ++j) { accA[j] = bias; accB[j] = bias; }
    const int y0 = 2 * py;
    for (int ic = 0; ic < 32; ++ic) {
        const float* inC = sIn + ic * 484;
#pragma unroll
        for (int ky = 0; ky < 5; ++ky) {
            const float* r0 = inC + (y0 + ky) * 22 + 6 * g;
            const float* r1 = r0 + 22;
            float ra[10], rb[10];
#pragma unroll
            for (int j = 0; j < 10; ++j) { ra[j] = r0[j]; rb[j] = r1[j]; }
            const float* wv = wB + ic * 25 + ky * 5;
#pragma unroll
            for (int kx = 0; kx < 5; ++kx) {
                float wk = wv[kx];
#pragma unroll
                for (int j = 0; j < 6; ++j) {
                    accA[j] = fmaf(ra[j + kx], wk, accA[j]);
                    accB[j] = fmaf(rb[j + kx], wk, accB[j]);
                }
            }
        }
    }
    float* o = g_s1 + ((bl * 32 + oc) * 9 + py) * 9 + 3 * g;
#pragma unroll
    for (int u = 0; u < 3; ++u) {
        float v0 = prelu(accA[2 * u], a);
        float v1 = prelu(accA[2 * u + 1], a);
        float v2 = prelu(accB[2 * u], a);
        float v3 = prelu(accB[2 * u + 1], a);
        o[u] = fmaxf(fmaxf(v0, v1), fmaxf(v2, v3));
    }
}

// ---------------------------------------------------------------------------
// Stage 2: conv(32->64, 4x4, pad1) + prelu + pool2   in: g_s1 (BL,32,9,9)
// grid = (BL,2) [oc half], block = 512 (ocl = tid&31, p=tid>>5: py=p>>2 px=p&3)
// smem: sIn[32][11][12] + sW[32][513]
// ---------------------------------------------------------------------------
__global__ void k_conv2(const float* __restrict__ w,
                        const float* __restrict__ b,
                        const float* __restrict__ ap) {
    extern __shared__ float smem[];
    float* sIn = smem;            // 32*132 = 4224
    float* sW  = smem + 4224;     // 32*513 = 16416
    const int bl   = blockIdx.x;
    const int half = blockIdx.y;
    const int tid  = threadIdx.x;

    for (int i = tid; i < 4224; i += 512) sIn[i] = 0.0f;
    __syncthreads();
    const float* src = g_s1 + bl * (32 * 81);
    for (int i = tid; i < 32 * 81; i += 512) {
        int ic = i / 81;
        int r  = (i / 9) % 9;
        int c  = i % 9;
        sIn[ic * 132 + (r + 1) * 12 + (c + 1)] = src[i];
    }
    for (int k = tid; k < 32 * 512; k += 512) {
        int ocl = k >> 9;
        sW[ocl * 513 + (k & 511)] = w[(half * 32 + ocl) * 512 + (k & 511)];
    }
    __syncthreads();

    const int ocl = tid & 31;
    const int p   = tid >> 5;
    const int py  = p >> 2;
    const int px  = p & 3;
    const int oc  = half * 32 + ocl;
    const float bias = b[oc];
    const float a = *ap;
    const float* wB = sW + ocl * 513;

    float accA[2], accB[2];
    accA[0] = accA[1] = accB[0] = accB[1] = bias;
    for (int ic = 0; ic < 32; ++ic) {
        const float* inC = sIn + ic * 132;
#pragma unroll
        for (int ky = 0; ky < 4; ++ky) {
            const float* r0 = inC + (2 * py + ky) * 12 + 2 * px;
            const float* r1 = r0 + 12;
            float ra[5], rb[5];
#pragma unroll
            for (int j = 0; j < 5; ++j) { ra[j] = r0[j]; rb[j] = r1[j]; }
            const float* wv = wB + ic * 16 + ky * 4;
#pragma unroll
            for (int kx = 0; kx < 4; ++kx) {
                float wk = wv[kx];
                accA[0] = fmaf(ra[kx],     wk, accA[0]);
                accA[1] = fmaf(ra[kx + 1], wk, accA[1]);
                accB[0] = fmaf(rb[kx],     wk, accB[0]);
                accB[1] = fmaf(rb[kx + 1], wk, accB[1]);
            }
        }
    }
    float v0 = prelu(accA[0], a);
    float v1 = prelu(accA[1], a);
    float v2 = prelu(accB[0], a);
    float v3 = prelu(accB[1], a);
    g_s2[((bl * 64 + oc) * 4 + py) * 4 + px] = fmaxf(fmaxf(v0, v1), fmaxf(v2, v3));
}

// ---------------------------------------------------------------------------
// Stage 3: conv(64->64, 3x3, pad0) + prelu + flatten  in: g_s2 (BL,64,4,4)
// grid = 384 (8 images/block), block = 256 (oc = tid>>2, pos = tid&3)
// smem: sW[64][577] + sIn[8][1024]
// ---------------------------------------------------------------------------
__global__ void k_conv3(const float* __restrict__ w,
                        const float* __restrict__ b,
                        const float* __restrict__ ap) {
    extern __shared__ float smem[];
    float* sW  = smem;             // 64*577 = 36928
    float* sIn = smem + 36928;     // 8*1024 = 8192
    const int tid = threadIdx.x;
    const int bl0 = blockIdx.x * 8;

    for (int k = tid; k < 64 * 576; k += 256) {
        int oc = k / 576;
        sW[oc * 577 + (k % 576)] = w[k];
    }
    const float* src = g_s2 + bl0 * 1024;
    for (int i = tid; i < 8192; i += 256) sIn[i] = src[i];
    __syncthreads();

    const int oc  = tid >> 2;
    const int pos = tid & 3;
    const int yy  = pos >> 1;
    const int xx  = pos & 1;
    const float bias = b[oc];
    const float a = *ap;

    float acc[8];
#pragma unroll
    for (int i = 0; i < 8; ++i) acc[i] = bias;

    for (int ic = 0; ic < 64; ++ic) {
        const float* wv = sW + oc * 577 + ic * 9;
        float wr[9];
#pragma unroll
        for (int j = 0; j < 9; ++j) wr[j] = wv[j];
#pragma unroll
        for (int img = 0; img < 8; ++img) {
            const float* ip = sIn + img * 1024 + ic * 16;
#pragma unroll
            for (int ky = 0; ky < 3; ++ky)
#pragma unroll
                for (int kx = 0; kx < 3; ++kx)
                    acc[img] = fmaf(ip[(yy + ky) * 4 + (xx + kx)], wr[ky * 3 + kx], acc[img]);
        }
    }
#pragma unroll
    for (int img = 0; img < 8; ++img) {
        g_s3[(bl0 + img) * 256 + oc * 4 + pos] = prelu(acc[img], a);
    }
}

// ---------------------------------------------------------------------------
// FC heads: per (b,l): 256 -> 128 (prelu a4[l]) -> 64 (prelu a5[l]) -> 4
// grid = BL, block = 128
// ---------------------------------------------------------------------------
__global__ void k_fc(const float* __restrict__ fc1_w, const float* __restrict__ fc1_b,
                     const float* __restrict__ a4,
                     const float* __restrict__ fc2_w, const float* __restrict__ fc2_b,
                     const float* __restrict__ a5,
                     const float* __restrict__ fc3_w, const float* __restrict__ fc3_b,
                     float* __restrict__ out) {
    __shared__ float feat[256];
    __shared__ float h1[128];
    __shared__ float h2[64];
    const int bl  = blockIdx.x;
    const int l   = bl % 6;
    const int tid = threadIdx.x;

    feat[tid]       = g_s3[bl * 256 + tid];
    feat[tid + 128] = g_s3[bl * 256 + 128 + tid];
    __syncthreads();

    {
        float acc = fc1_b[l * 128 + tid];
        const float* W = fc1_w + l * 256 * 128 + tid;
#pragma unroll 8
        for (int i = 0; i < 256; ++i) acc = fmaf(feat[i], W[i * 128], acc);
        float av = a4[l];
        h1[tid] = prelu(acc, av);
    }
    __syncthreads();
    if (tid < 64) {
        float acc = fc2_b[l * 64 + tid];
        const float* W = fc2_w + l * 128 * 64 + tid;
#pragma unroll 8
        for (int i = 0; i < 128; ++i) acc = fmaf(h1[i], W[i * 64], acc);
        float av = a5[l];
        h2[tid] = prelu(acc, av);
    }
    __syncthreads();
    if (tid < 4) {
        float acc = fc3_b[l * 4 + tid];
        const float* W = fc3_w + l * 64 * 4 + tid;
#pragma unroll
        for (int i = 0; i < 64; ++i) acc = fmaf(h2[i], W[i * 4], acc);
        out[bl * 4 + tid] = acc;
    }
}

// ---------------------------------------------------------------------------
extern "C" void kernel_launch(void* const* d_in, const int* in_sizes, int n_in,
                              void* d_out, int out_size) {
    const float* x     = (const float*)d_in[0];
    const float* w0    = (const float*)d_in[1];
    const float* b0    = (const float*)d_in[2];
    const float* w1    = (const float*)d_in[3];
    const float* b1    = (const float*)d_in[4];
    const float* w2    = (const float*)d_in[5];
    const float* b2    = (const float*)d_in[6];
    const float* w3    = (const float*)d_in[7];
    const float* b3    = (const float*)d_in[8];
    const float* a0    = (const float*)d_in[9];
    const float* a1    = (const float*)d_in[10];
    const float* a2    = (const float*)d_in[11];
    const float* a3    = (const float*)d_in[12];
    const float* fc1_w = (const float*)d_in[13];
    const float* fc1_b = (const float*)d_in[14];
    const float* a4    = (const float*)d_in[15];
    const float* fc2_w = (const float*)d_in[16];
    const float* fc2_b = (const float*)d_in[17];
    const float* a5    = (const float*)d_in[18];
    const float* fc3_w = (const float*)d_in[19];
    const float* fc3_b = (const float*)d_in[20];
    float* out = (float*)d_out;

    const int smem0 = (8464 + 3232) * 4;            // 46,784 B
    const int smem1 = (15488 + 12816) * 4;          // 113,216 B
    const int smem2 = (4224 + 16416) * 4;           // 82,560 B
    const int smem3 = (36928 + 8192) * 4;           // 180,480 B

    cudaFuncSetAttribute(k_conv0, cudaFuncAttributeMaxDynamicSharedMemorySize, smem0);
    cudaFuncSetAttribute(k_conv1, cudaFuncAttributeMaxDynamicSharedMemorySize, smem1);
    cudaFuncSetAttribute(k_conv2, cudaFuncAttributeMaxDynamicSharedMemorySize, smem2);
    cudaFuncSetAttribute(k_conv3, cudaFuncAttributeMaxDynamicSharedMemorySize, smem3);

    k_conv0<<<BL, 224, smem0>>>(x, w0, b0, a0);
    k_conv1<<<dim3(BL, 2), 432, smem1>>>(w1, b1, a1);
    k_conv2<<<dim3(BL, 2), 512, smem2>>>(w2, b2, a2);
    k_conv3<<<BL / 8, 256, smem3>>>(w3, b3, a3);
    k_fc<<<BL, 128>>>(fc1_w, fc1_b, a4, fc2_w, fc2_b, a5, fc3_w, fc3_b, out);
}